// round 9
// baseline (speedup 1.0000x reference)
#include <cuda_runtime.h>
#include <cstdint>

// Problem constants
#define B   32
#define C   256
#define H   56
#define W   56
#define OH  28
#define OW  28
#define CO  256           // outputs per half
#define NW  8             // 256 bits -> 8 uint32 words
#define NELEM_PER_C (B*H*W)  // 100352

// -------- device scratch (no allocations allowed) --------
__device__ float    g_partial[C][B][2];          // per (channel, batch): sum, sumsq
__device__ float    g_lo[C];                     // binarize window: +1 iff lo <= v <= hi
__device__ float    g_hi[C];
__device__ int      g_fast;                      // 1 if all gamma > 0 (lo-only compare)
__device__ unsigned g_wpack[2*CO][NW];           // rows 0..255 = w1, 256..511 = w2

// ============================================================
// Kernel 1: stats partials (one warp per (b,c) plane) + weight pack.
// grid 1088: blocks 0..1023 stats, 1024..1087 wpack.
// ============================================================
__global__ __launch_bounds__(256) void stats_wpack_kernel(const float* __restrict__ x,
                                                          const float* __restrict__ w1,
                                                          const float* __restrict__ w2) {
    int lane = threadIdx.x & 31;
    if (blockIdx.x >= 1024) {
        int warp = ((blockIdx.x - 1024) * 256 + threadIdx.x) >> 5;   // 0..511
        const float* w = (warp < CO) ? (w1 + (size_t)warp * C)
                                     : (w2 + (size_t)(warp - CO) * C);
        #pragma unroll
        for (int j = 0; j < NW; j++) {
            float v = __ldcs(&w[j * 32 + lane]);
            unsigned m = __ballot_sync(0xffffffffu, v >= 0.f);
            if (lane == 0) g_wpack[warp][j] = m;
        }
        return;
    }
    int wid = (blockIdx.x * 256 + threadIdx.x) >> 5;  // plane 0..8191
    int b = wid >> 8, c = wid & 255;
    const float4* p = reinterpret_cast<const float4*>(x + ((size_t)b * C + c) * (H * W));
    float s0 = 0.f, s1 = 0.f, q0 = 0.f, q1 = 0.f;
    #pragma unroll 4
    for (int i = lane; i < (H * W) / 4; i += 32) {
        float4 v = __ldg(p + i);
        s0 += v.x + v.y;
        s1 += v.z + v.w;
        q0 += v.x * v.x + v.y * v.y;
        q1 += v.z * v.z + v.w * v.w;
    }
    float s = s0 + s1, q = q0 + q1;
    #pragma unroll
    for (int o = 16; o > 0; o >>= 1) {
        s += __shfl_down_sync(0xffffffffu, s, o);
        q += __shfl_down_sync(0xffffffffu, q, o);
    }
    if (lane == 0) {
        g_partial[c][b][0] = s;
        g_partial[c][b][1] = q;
    }
}

// ============================================================
// Kernel 2: finalize stats -> per-channel [lo, hi] window + fast flag
// ============================================================
__global__ __launch_bounds__(256) void thr_kernel(const float* __restrict__ gamma,
                                                  const float* __restrict__ beta) {
    int c = threadIdx.x;
    float s = 0.f, sq = 0.f;
    #pragma unroll
    for (int k = 0; k < B; k++) { s += g_partial[c][k][0]; sq += g_partial[c][k][1]; }
    const float N = (float)NELEM_PER_C;
    float mean = s / N;
    float var  = sq / N - mean * mean;
    if (var < 0.f) var = 0.f;
    float inv = rsqrtf(var + 1e-5f);
    float g = gamma[c], bt = beta[c];
    const float INF = __int_as_float(0x7f800000);
    float lo, hi;
    if (g > 0.f)      { lo = mean - bt / (inv * g); hi =  INF; }
    else if (g < 0.f) { hi = mean - bt / (inv * g); lo = -INF; }
    else if (bt >= 0.f) { lo = -INF; hi =  INF; }
    else                { lo =  INF; hi = -INF; }
    g_lo[c] = lo;
    g_hi[c] = hi;

    __shared__ int sflag;
    if (threadIdx.x == 0) sflag = 1;
    __syncthreads();
    unsigned warp_ok = __ballot_sync(0xffffffffu, g > 0.f);
    if ((threadIdx.x & 31) == 0 && warp_ok != 0xffffffffu) atomicAnd(&sflag, 0);
    __syncthreads();
    if (threadIdx.x == 0) g_fast = sflag;
}

// ============================================================
// Kernel 3 (FUSED): binarize+pack into smem, then XNOR-popcount GEMM.
// grid (B, OH, 2 halves), block 256 = 8 warps.
// - __launch_bounds__(256, 8): cap regs at 32 -> 8 blocks/SM for phase overlap
// - b reversed vs launch order: earliest blocks read the x tail, which stats
//   touched most recently (still L2-resident), staying ahead of out-evictions
// - out stores streaming (__stcs): write-once lines, keep L2 for x
// ============================================================
__global__ __launch_bounds__(256, 8) void fused_kernel(const float* __restrict__ x,
                                                       float* __restrict__ out) {
    int b = (B - 1) - blockIdx.x;   // reverse order for L2 temporal locality
    int oh = blockIdx.y, half = blockIdx.z;
    int j    = threadIdx.x >> 5;
    int lane = threadIdx.x & 31;
    int h = 2 * oh + half;

    __shared__ uint4 sa4[OW * NW / 4];   // 896 B packed activations
    __shared__ uint4 sw4[CO * NW / 4];   // 8 KB packed weights (this half)
    unsigned* sa = reinterpret_cast<unsigned*>(sa4);

    // ---- Phase A: binarize + register-pack (LDGs first) ----
    {
        const size_t rowstep = (size_t)H * W;
        int k = lane < OW ? lane : OW - 1;            // clamp so all lanes can shfl
        const float* base = x + (((size_t)b * C + j * 32) * H + h) * W;
        unsigned bits = 0;
        if (g_fast) {
            float lo_mine = g_lo[j * 32 + lane];      // one value per lane
            #pragma unroll 8
            for (int r = 0; r < 32; r++) {
                float2 v = __ldg(reinterpret_cast<const float2*>(base + r * rowstep) + k);
                float val = half ? v.y : v.x;
                float lo_r = __shfl_sync(0xffffffffu, lo_mine, r);
                bits |= (val >= lo_r ? 1u : 0u) << r;
            }
        } else {
            #pragma unroll 8
            for (int r = 0; r < 32; r++) {
                int c = j * 32 + r;
                float2 v = __ldg(reinterpret_cast<const float2*>(base + r * rowstep) + k);
                float val = half ? v.y : v.x;
                bool pred = (val >= g_lo[c]) && (val <= g_hi[c]);
                bits |= (pred ? 1u : 0u) << r;
            }
        }
        if (lane < OW) sa[lane * NW + j] = bits;
    }

    // ---- stage weights (L2-hot) ----
    {
        const uint4* wsrc = reinterpret_cast<const uint4*>(&g_wpack[half * CO][0]);
        #pragma unroll
        for (int i = 0; i < (CO * NW / 4) / 256; i++)
            sw4[i * 256 + threadIdx.x] = wsrc[i * 256 + threadIdx.x];
    }
    __syncthreads();

    // ---- Phase B: popcount GEMM (vector LDS, streaming stores) ----
    if (lane >= OW) return;

    uint4 av0 = sa4[lane * 2 + 0];
    uint4 av1 = sa4[lane * 2 + 1];
    unsigned a0 = av0.x, a1 = av0.y, a2 = av0.z, a3 = av0.w;
    unsigned a4 = av1.x, a5 = av1.y, a6 = av1.z, a7 = av1.w;

    float* op = out + ((((size_t)b * 2 * CO + half * CO) * OH + oh) * OW) + lane;
    #pragma unroll 8
    for (int oo = 0; oo < CO / 8; oo++) {
        int o = oo * 8 + j;
        uint4 wv0 = sw4[o * 2 + 0];
        uint4 wv1 = sw4[o * 2 + 1];
        int s = __popc(a0 ^ wv0.x) + __popc(a1 ^ wv0.y)
              + __popc(a2 ^ wv0.z) + __popc(a3 ^ wv0.w)
              + __popc(a4 ^ wv1.x) + __popc(a5 ^ wv1.y)
              + __popc(a6 ^ wv1.z) + __popc(a7 ^ wv1.w);
        __stcs(op + (size_t)o * (OH * OW), (float)(C - 2 * s));
    }
}

// ============================================================
extern "C" void kernel_launch(void* const* d_in, const int* in_sizes, int n_in,
                              void* d_out, int out_size) {
    const float* x     = (const float*)d_in[0];
    const float* gamma = (const float*)d_in[1];
    const float* beta  = (const float*)d_in[2];
    const float* w1    = (const float*)d_in[3];
    const float* w2    = (const float*)d_in[4];
    float* out = (float*)d_out;

    stats_wpack_kernel<<<1088, 256>>>(x, w1, w2);
    thr_kernel<<<1, 256>>>(gamma, beta);
    fused_kernel<<<dim3(B, OH, 2), 256>>>(x, out);
}

// round 10
// speedup vs baseline: 1.0089x; 1.0089x over previous
#include <cuda_runtime.h>
#include <cstdint>

// Problem constants
#define B   32
#define C   256
#define H   56
#define W   56
#define OH  28
#define OW  28
#define CO  256           // outputs per half
#define NW  8             // 256 bits -> 8 uint32 words
#define NELEM_PER_C (B*H*W)  // 100352

// -------- device scratch (no allocations allowed) --------
__device__ float    g_partial[C][B][2];          // per (channel, batch): sum, sumsq
__device__ float    g_lo[C];                     // binarize window: +1 iff lo <= v <= hi
__device__ float    g_hi[C];
__device__ int      g_fast;                      // 1 if all gamma > 0 (lo-only compare)
__device__ unsigned g_wpack[2*CO][NW];           // rows 0..255 = w1, 256..511 = w2

// ============================================================
// Kernel 1: stats partials (one warp per (b,c) plane) + weight pack.
// grid 1088: blocks 0..1023 stats, 1024..1087 wpack.
// ============================================================
__global__ __launch_bounds__(256) void stats_wpack_kernel(const float* __restrict__ x,
                                                          const float* __restrict__ w1,
                                                          const float* __restrict__ w2) {
    int lane = threadIdx.x & 31;
    if (blockIdx.x >= 1024) {
        int warp = ((blockIdx.x - 1024) * 256 + threadIdx.x) >> 5;   // 0..511
        const float* w = (warp < CO) ? (w1 + (size_t)warp * C)
                                     : (w2 + (size_t)(warp - CO) * C);
        #pragma unroll
        for (int j = 0; j < NW; j++) {
            float v = w[j * 32 + lane];
            unsigned m = __ballot_sync(0xffffffffu, v >= 0.f);
            if (lane == 0) g_wpack[warp][j] = m;
        }
        return;
    }
    int wid = (blockIdx.x * 256 + threadIdx.x) >> 5;  // plane 0..8191
    int b = wid >> 8, c = wid & 255;
    const float4* p = reinterpret_cast<const float4*>(x + ((size_t)b * C + c) * (H * W));
    float s0 = 0.f, s1 = 0.f, q0 = 0.f, q1 = 0.f;
    #pragma unroll 4
    for (int i = lane; i < (H * W) / 4; i += 32) {
        float4 v = p[i];
        s0 += v.x + v.y;
        s1 += v.z + v.w;
        q0 += v.x * v.x + v.y * v.y;
        q1 += v.z * v.z + v.w * v.w;
    }
    float s = s0 + s1, q = q0 + q1;
    #pragma unroll
    for (int o = 16; o > 0; o >>= 1) {
        s += __shfl_down_sync(0xffffffffu, s, o);
        q += __shfl_down_sync(0xffffffffu, q, o);
    }
    if (lane == 0) {
        g_partial[c][b][0] = s;
        g_partial[c][b][1] = q;
    }
}

// ============================================================
// Kernel 2: finalize stats -> per-channel [lo, hi] window + fast flag
// ============================================================
__global__ __launch_bounds__(256) void thr_kernel(const float* __restrict__ gamma,
                                                  const float* __restrict__ beta) {
    int c = threadIdx.x;
    float s = 0.f, sq = 0.f;
    #pragma unroll
    for (int k = 0; k < B; k++) { s += g_partial[c][k][0]; sq += g_partial[c][k][1]; }
    const float N = (float)NELEM_PER_C;
    float mean = s / N;
    float var  = sq / N - mean * mean;
    if (var < 0.f) var = 0.f;
    float inv = rsqrtf(var + 1e-5f);
    float g = gamma[c], bt = beta[c];
    const float INF = __int_as_float(0x7f800000);
    float lo, hi;
    if (g > 0.f)      { lo = mean - bt / (inv * g); hi =  INF; }
    else if (g < 0.f) { hi = mean - bt / (inv * g); lo = -INF; }
    else if (bt >= 0.f) { lo = -INF; hi =  INF; }
    else                { lo =  INF; hi = -INF; }
    g_lo[c] = lo;
    g_hi[c] = hi;

    __shared__ int sflag;
    if (threadIdx.x == 0) sflag = 1;
    __syncthreads();
    unsigned warp_ok = __ballot_sync(0xffffffffu, g > 0.f);
    if ((threadIdx.x & 31) == 0 && warp_ok != 0xffffffffu) atomicAnd(&sflag, 0);
    __syncthreads();
    if (threadIdx.x == 0) g_fast = sflag;
}

// ============================================================
// Kernel 3 (FUSED, oh-PAIRED): binarize+pack two oh rows, then popc GEMM
// for both. grid (B, OH/2, 2), block 256 = 8 warps.
// The two output rows per (o) are contiguous (224B, 7 full 32B sectors,
// 224B-aligned) -> no partial-sector DRAM read-modify-write.
// Weight stage + per-o LDS amortized over 2 positions.
// ============================================================
__global__ __launch_bounds__(256) void fused_kernel(const float* __restrict__ x,
                                                    float* __restrict__ out) {
    int b = blockIdx.x, ohg = blockIdx.y, half = blockIdx.z;
    int j    = threadIdx.x >> 5;
    int lane = threadIdx.x & 31;

    __shared__ uint4 sa4[2][OW * NW / 4];  // 1.75 KB packed activations (2 rows)
    __shared__ uint4 sw4[CO * NW / 4];     // 8 KB packed weights (this half)
    unsigned (*sa)[OW * NW] = reinterpret_cast<unsigned (*)[OW * NW]>(sa4);

    // ---- Phase A: binarize + register-pack, for oh = 2*ohg and 2*ohg+1 ----
    {
        const size_t rowstep = (size_t)H * W;
        int k = lane < OW ? lane : OW - 1;            // clamp so all lanes can shfl
        float lo_mine = g_lo[j * 32 + lane];          // one value per lane
        float hi_mine = g_hi[j * 32 + lane];
        int fast = g_fast;
        #pragma unroll
        for (int t = 0; t < 2; t++) {
            int h = 2 * (2 * ohg + t) + half;
            const float* base = x + (((size_t)b * C + j * 32) * H + h) * W;
            unsigned bits = 0;
            if (fast) {
                #pragma unroll 8
                for (int r = 0; r < 32; r++) {
                    float2 v = reinterpret_cast<const float2*>(base + r * rowstep)[k];
                    float val = half ? v.y : v.x;
                    float lo_r = __shfl_sync(0xffffffffu, lo_mine, r);
                    bits |= (val >= lo_r ? 1u : 0u) << r;
                }
            } else {
                #pragma unroll 8
                for (int r = 0; r < 32; r++) {
                    float2 v = reinterpret_cast<const float2*>(base + r * rowstep)[k];
                    float val = half ? v.y : v.x;
                    float lo_r = __shfl_sync(0xffffffffu, lo_mine, r);
                    float hi_r = __shfl_sync(0xffffffffu, hi_mine, r);
                    bool pred = (val >= lo_r) && (val <= hi_r);
                    bits |= (pred ? 1u : 0u) << r;
                }
            }
            if (lane < OW) sa[t][lane * NW + j] = bits;
        }
    }

    // ---- stage weights (L2-hot after first wave) ----
    {
        const uint4* wsrc = reinterpret_cast<const uint4*>(&g_wpack[half * CO][0]);
        #pragma unroll
        for (int i = 0; i < (CO * NW / 4) / 256; i++)
            sw4[i * 256 + threadIdx.x] = wsrc[i * 256 + threadIdx.x];
    }
    __syncthreads();

    // ---- Phase B: popcount GEMM for both rows ----
    if (lane >= OW) return;

    uint4 p0 = sa4[0][lane * 2 + 0], p1 = sa4[0][lane * 2 + 1];
    uint4 q0 = sa4[1][lane * 2 + 0], q1 = sa4[1][lane * 2 + 1];

    // base of the 2-row stripe: rows 2*ohg, 2*ohg+1 of this (b, half) plane set
    float* op = out + ((((size_t)b * 2 * CO + half * CO) * OH + 2 * ohg) * OW) + lane;
    #pragma unroll 8
    for (int oo = 0; oo < CO / 8; oo++) {
        int o = oo * 8 + j;
        uint4 wv0 = sw4[o * 2 + 0];
        uint4 wv1 = sw4[o * 2 + 1];
        int s0 = __popc(p0.x ^ wv0.x) + __popc(p0.y ^ wv0.y)
               + __popc(p0.z ^ wv0.z) + __popc(p0.w ^ wv0.w)
               + __popc(p1.x ^ wv1.x) + __popc(p1.y ^ wv1.y)
               + __popc(p1.z ^ wv1.z) + __popc(p1.w ^ wv1.w);
        int s1 = __popc(q0.x ^ wv0.x) + __popc(q0.y ^ wv0.y)
               + __popc(q0.z ^ wv0.z) + __popc(q0.w ^ wv0.w)
               + __popc(q1.x ^ wv1.x) + __popc(q1.y ^ wv1.y)
               + __popc(q1.z ^ wv1.z) + __popc(q1.w ^ wv1.w);
        float* po = op + (size_t)o * (OH * OW);
        po[0]  = (float)(C - 2 * s0);   // row 2*ohg
        po[OW] = (float)(C - 2 * s1);   // row 2*ohg+1 (contiguous stripe)
    }
}

// ============================================================
extern "C" void kernel_launch(void* const* d_in, const int* in_sizes, int n_in,
                              void* d_out, int out_size) {
    const float* x     = (const float*)d_in[0];
    const float* gamma = (const float*)d_in[1];
    const float* beta  = (const float*)d_in[2];
    const float* w1    = (const float*)d_in[3];
    const float* w2    = (const float*)d_in[4];
    float* out = (float*)d_out;

    stats_wpack_kernel<<<1088, 256>>>(x, w1, w2);
    thr_kernel<<<1, 256>>>(gamma, beta);
    fused_kernel<<<dim3(B, OH / 2, 2), 256>>>(x, out);
}

// round 11
// speedup vs baseline: 1.1652x; 1.1549x over previous
#include <cuda_runtime.h>
#include <cstdint>

// Problem constants
#define B   32
#define C   256
#define H   56
#define W   56
#define OH  28
#define OW  28
#define CO  256           // outputs per half
#define NW  8             // 256 bits -> 8 uint32 words
#define NELEM_PER_C (B*H*W)  // 100352

// -------- device scratch (no allocations allowed) --------
__device__ float    g_partial[C][B][2];          // per (channel, batch): sum, sumsq
__device__ float    g_lo[C];                     // binarize window: +1 iff lo <= v <= hi
__device__ float    g_hi[C];
__device__ int      g_fast;                      // 1 if all gamma > 0 (lo-only compare)
__device__ unsigned g_wpack[2*CO][NW];           // rows 0..255 = w1, 256..511 = w2

// ============================================================
// Kernel 1: stats partials (one warp per (b,c) plane) + weight pack.
// grid 1088: blocks 0..1023 stats, 1024..1087 wpack.
// ============================================================
__global__ __launch_bounds__(256) void stats_wpack_kernel(const float* __restrict__ x,
                                                          const float* __restrict__ w1,
                                                          const float* __restrict__ w2) {
    int lane = threadIdx.x & 31;
    if (blockIdx.x >= 1024) {
        int warp = ((blockIdx.x - 1024) * 256 + threadIdx.x) >> 5;   // 0..511
        const float* w = (warp < CO) ? (w1 + (size_t)warp * C)
                                     : (w2 + (size_t)(warp - CO) * C);
        #pragma unroll
        for (int j = 0; j < NW; j++) {
            float v = w[j * 32 + lane];
            unsigned m = __ballot_sync(0xffffffffu, v >= 0.f);
            if (lane == 0) g_wpack[warp][j] = m;
        }
        return;
    }
    int wid = (blockIdx.x * 256 + threadIdx.x) >> 5;  // plane 0..8191
    int b = wid >> 8, c = wid & 255;
    const float4* p = reinterpret_cast<const float4*>(x + ((size_t)b * C + c) * (H * W));
    float s0 = 0.f, s1 = 0.f, q0 = 0.f, q1 = 0.f;
    #pragma unroll 4
    for (int i = lane; i < (H * W) / 4; i += 32) {
        float4 v = p[i];
        s0 += v.x + v.y;
        s1 += v.z + v.w;
        q0 += v.x * v.x + v.y * v.y;
        q1 += v.z * v.z + v.w * v.w;
    }
    float s = s0 + s1, q = q0 + q1;
    #pragma unroll
    for (int o = 16; o > 0; o >>= 1) {
        s += __shfl_down_sync(0xffffffffu, s, o);
        q += __shfl_down_sync(0xffffffffu, q, o);
    }
    if (lane == 0) {
        g_partial[c][b][0] = s;
        g_partial[c][b][1] = q;
    }
}

// ============================================================
// Kernel 2: finalize stats -> per-channel [lo, hi] window + fast flag
// ============================================================
__global__ __launch_bounds__(256) void thr_kernel(const float* __restrict__ gamma,
                                                  const float* __restrict__ beta) {
    int c = threadIdx.x;
    float s = 0.f, sq = 0.f;
    #pragma unroll
    for (int k = 0; k < B; k++) { s += g_partial[c][k][0]; sq += g_partial[c][k][1]; }
    const float N = (float)NELEM_PER_C;
    float mean = s / N;
    float var  = sq / N - mean * mean;
    if (var < 0.f) var = 0.f;
    float inv = rsqrtf(var + 1e-5f);
    float g = gamma[c], bt = beta[c];
    const float INF = __int_as_float(0x7f800000);
    float lo, hi;
    if (g > 0.f)      { lo = mean - bt / (inv * g); hi =  INF; }
    else if (g < 0.f) { hi = mean - bt / (inv * g); lo = -INF; }
    else if (bt >= 0.f) { lo = -INF; hi =  INF; }
    else                { lo =  INF; hi = -INF; }
    g_lo[c] = lo;
    g_hi[c] = hi;

    __shared__ int sflag;
    if (threadIdx.x == 0) sflag = 1;
    __syncthreads();
    unsigned warp_ok = __ballot_sync(0xffffffffu, g > 0.f);
    if ((threadIdx.x & 31) == 0 && warp_ok != 0xffffffffu) atomicAnd(&sflag, 0);
    __syncthreads();
    if (threadIdx.x == 0) g_fast = sflag;
}

// ============================================================
// Kernel 3 (FUSED): binarize+pack into smem, then XNOR-popcount GEMM.
// grid (OH, B, 2): oh is the FASTEST block axis, so co-scheduled blocks
// read adjacent x rows (same DRAM pages) and write adjacent 112B output
// stripes (which merge into full L2 lines/sectors). Structure otherwise
// identical to the proven round-4/6 baseline.
// ============================================================
__global__ __launch_bounds__(256) void fused_kernel(const float* __restrict__ x,
                                                    float* __restrict__ out) {
    int oh = blockIdx.x, b = blockIdx.y, half = blockIdx.z;
    int j    = threadIdx.x >> 5;
    int lane = threadIdx.x & 31;
    int h = 2 * oh + half;

    __shared__ uint4 sa4[OW * NW / 4];   // 896 B packed activations
    __shared__ uint4 sw4[CO * NW / 4];   // 8 KB packed weights (this half)
    unsigned* sa = reinterpret_cast<unsigned*>(sa4);

    // ---- Phase A: binarize + register-pack (LDGs first) ----
    {
        const size_t rowstep = (size_t)H * W;
        int k = lane < OW ? lane : OW - 1;            // clamp so all lanes can shfl
        const float* base = x + (((size_t)b * C + j * 32) * H + h) * W;
        unsigned bits = 0;
        if (g_fast) {
            float lo_mine = g_lo[j * 32 + lane];      // one value per lane
            #pragma unroll 8
            for (int r = 0; r < 32; r++) {
                float2 v = reinterpret_cast<const float2*>(base + r * rowstep)[k];
                float val = half ? v.y : v.x;
                float lo_r = __shfl_sync(0xffffffffu, lo_mine, r);
                bits |= (val >= lo_r ? 1u : 0u) << r;
            }
        } else {
            #pragma unroll 8
            for (int r = 0; r < 32; r++) {
                int c = j * 32 + r;
                float2 v = reinterpret_cast<const float2*>(base + r * rowstep)[k];
                float val = half ? v.y : v.x;
                bool pred = (val >= g_lo[c]) && (val <= g_hi[c]);
                bits |= (pred ? 1u : 0u) << r;
            }
        }
        if (lane < OW) sa[lane * NW + j] = bits;
    }

    // ---- stage weights (L2-hot after first wave) ----
    {
        const uint4* wsrc = reinterpret_cast<const uint4*>(&g_wpack[half * CO][0]);
        #pragma unroll
        for (int i = 0; i < (CO * NW / 4) / 256; i++)
            sw4[i * 256 + threadIdx.x] = wsrc[i * 256 + threadIdx.x];
    }
    __syncthreads();

    // ---- Phase B: popcount GEMM (vector LDS) ----
    if (lane >= OW) return;

    uint4 av0 = sa4[lane * 2 + 0];
    uint4 av1 = sa4[lane * 2 + 1];
    unsigned a0 = av0.x, a1 = av0.y, a2 = av0.z, a3 = av0.w;
    unsigned a4 = av1.x, a5 = av1.y, a6 = av1.z, a7 = av1.w;

    float* op = out + ((((size_t)b * 2 * CO + half * CO) * OH + oh) * OW) + lane;
    #pragma unroll 8
    for (int oo = 0; oo < CO / 8; oo++) {
        int o = oo * 8 + j;
        uint4 wv0 = sw4[o * 2 + 0];
        uint4 wv1 = sw4[o * 2 + 1];
        int s = __popc(a0 ^ wv0.x) + __popc(a1 ^ wv0.y)
              + __popc(a2 ^ wv0.z) + __popc(a3 ^ wv0.w)
              + __popc(a4 ^ wv1.x) + __popc(a5 ^ wv1.y)
              + __popc(a6 ^ wv1.z) + __popc(a7 ^ wv1.w);
        op[(size_t)o * (OH * OW)] = (float)(C - 2 * s);
    }
}

// ============================================================
extern "C" void kernel_launch(void* const* d_in, const int* in_sizes, int n_in,
                              void* d_out, int out_size) {
    const float* x     = (const float*)d_in[0];
    const float* gamma = (const float*)d_in[1];
    const float* beta  = (const float*)d_in[2];
    const float* w1    = (const float*)d_in[3];
    const float* w2    = (const float*)d_in[4];
    float* out = (float*)d_out;

    stats_wpack_kernel<<<1088, 256>>>(x, w1, w2);
    thr_kernel<<<1, 256>>>(gamma, beta);
    fused_kernel<<<dim3(OH, B, 2), 256>>>(x, out);
}

// round 12
// speedup vs baseline: 1.1706x; 1.0047x over previous
#include <cuda_runtime.h>
#include <cstdint>

// Problem constants
#define B   32
#define C   256
#define H   56
#define W   56
#define OH  28
#define OW  28
#define CO  256           // outputs per half
#define NW  8             // 256 bits -> 8 uint32 words
#define NELEM_PER_C (B*H*W)  // 100352

// -------- device scratch (no allocations allowed) --------
__device__ float    g_partial[C][B][2];          // per (channel, batch): sum, sumsq
__device__ float    g_lo[C];                     // binarize window: +1 iff lo <= v <= hi
__device__ float    g_hi[C];
__device__ int      g_fast;                      // 1 if all gamma > 0 (lo-only compare)
__device__ unsigned g_wpack[2*CO][NW];           // rows 0..255 = w1, 256..511 = w2
__device__ unsigned g_count;                     // stats-block arrival counter (reset each run)

// ============================================================
// Kernel 1: stats partials (one warp per (b,c) plane) + weight pack
// + LAST-BLOCK threshold finalize (replaces separate thr_kernel).
// grid 1088: blocks 0..1023 stats, 1024..1087 wpack.
// ============================================================
__global__ __launch_bounds__(256) void stats_wpack_kernel(const float* __restrict__ x,
                                                          const float* __restrict__ w1,
                                                          const float* __restrict__ w2,
                                                          const float* __restrict__ gamma,
                                                          const float* __restrict__ beta) {
    int lane = threadIdx.x & 31;
    if (blockIdx.x >= 1024) {
        // ---- weight pack ----
        int warp = ((blockIdx.x - 1024) * 256 + threadIdx.x) >> 5;   // 0..511
        const float* w = (warp < CO) ? (w1 + (size_t)warp * C)
                                     : (w2 + (size_t)(warp - CO) * C);
        #pragma unroll
        for (int j = 0; j < NW; j++) {
            float v = w[j * 32 + lane];
            unsigned m = __ballot_sync(0xffffffffu, v >= 0.f);
            if (lane == 0) g_wpack[warp][j] = m;
        }
        return;
    }
    // ---- stats: plane id = warp id ----
    int wid = (blockIdx.x * 256 + threadIdx.x) >> 5;  // plane 0..8191
    int b = wid >> 8, c = wid & 255;
    const float4* p = reinterpret_cast<const float4*>(x + ((size_t)b * C + c) * (H * W));
    float s0 = 0.f, s1 = 0.f, q0 = 0.f, q1 = 0.f;
    // 784 float4 per plane = 24 full warp-iterations + 16-lane tail
    #pragma unroll 8
    for (int it = 0; it < 24; it++) {
        float4 v = p[lane + it * 32];
        s0 += v.x + v.y;
        s1 += v.z + v.w;
        q0 += v.x * v.x + v.y * v.y;
        q1 += v.z * v.z + v.w * v.w;
    }
    if (lane < 16) {
        float4 v = p[lane + 768];
        s0 += v.x + v.y;
        s1 += v.z + v.w;
        q0 += v.x * v.x + v.y * v.y;
        q1 += v.z * v.z + v.w * v.w;
    }
    float s = s0 + s1, q = q0 + q1;
    #pragma unroll
    for (int o = 16; o > 0; o >>= 1) {
        s += __shfl_down_sync(0xffffffffu, s, o);
        q += __shfl_down_sync(0xffffffffu, q, o);
    }
    if (lane == 0) {
        g_partial[c][b][0] = s;
        g_partial[c][b][1] = q;
    }

    // ---- last-arriving stats block finalizes thresholds ----
    __threadfence();
    __shared__ int is_last;
    if (threadIdx.x == 0)
        is_last = (atomicAdd(&g_count, 1u) == 1023u);
    __syncthreads();
    if (!is_last) return;

    {
        int c2 = threadIdx.x;                     // 256 threads = 256 channels
        float ss = 0.f, sq = 0.f;
        #pragma unroll
        for (int k = 0; k < B; k++) { ss += g_partial[c2][k][0]; sq += g_partial[c2][k][1]; }
        const float N = (float)NELEM_PER_C;
        float mean = ss / N;
        float var  = sq / N - mean * mean;
        if (var < 0.f) var = 0.f;
        float inv = rsqrtf(var + 1e-5f);
        float g = gamma[c2], bt = beta[c2];
        const float INF = __int_as_float(0x7f800000);
        float lo, hi;
        if (g > 0.f)      { lo = mean - bt / (inv * g); hi =  INF; }
        else if (g < 0.f) { hi = mean - bt / (inv * g); lo = -INF; }
        else if (bt >= 0.f) { lo = -INF; hi =  INF; }
        else                { lo =  INF; hi = -INF; }
        g_lo[c2] = lo;
        g_hi[c2] = hi;

        __shared__ int sflag;
        if (threadIdx.x == 0) sflag = 1;
        __syncthreads();
        unsigned warp_ok = __ballot_sync(0xffffffffu, g > 0.f);
        if ((threadIdx.x & 31) == 0 && warp_ok != 0xffffffffu) atomicAnd(&sflag, 0);
        __syncthreads();
        if (threadIdx.x == 0) {
            g_fast = sflag;
            g_count = 0;          // reset for next graph replay
        }
    }
}

// ============================================================
// Kernel 2 (FUSED): binarize+pack into smem, then XNOR-popcount GEMM.
// grid (OH, B, 2): oh fastest -> co-scheduled blocks read adjacent x rows
// and write adjacent output stripes (round-11 win, unchanged).
// x loads via __ldcg (single-use rows, skip L1 allocation).
// ============================================================
__global__ __launch_bounds__(256) void fused_kernel(const float* __restrict__ x,
                                                    float* __restrict__ out) {
    int oh = blockIdx.x, b = blockIdx.y, half = blockIdx.z;
    int j    = threadIdx.x >> 5;
    int lane = threadIdx.x & 31;
    int h = 2 * oh + half;

    __shared__ uint4 sa4[OW * NW / 4];   // 896 B packed activations
    __shared__ uint4 sw4[CO * NW / 4];   // 8 KB packed weights (this half)
    unsigned* sa = reinterpret_cast<unsigned*>(sa4);

    // ---- Phase A: binarize + register-pack (LDGs first) ----
    {
        const size_t rowstep = (size_t)H * W;
        int k = lane < OW ? lane : OW - 1;            // clamp so all lanes can shfl
        const float* base = x + (((size_t)b * C + j * 32) * H + h) * W;
        unsigned bits = 0;
        if (g_fast) {
            float lo_mine = g_lo[j * 32 + lane];      // one value per lane
            #pragma unroll 8
            for (int r = 0; r < 32; r++) {
                float2 v = __ldcg(reinterpret_cast<const float2*>(base + r * rowstep) + k);
                float val = half ? v.y : v.x;
                float lo_r = __shfl_sync(0xffffffffu, lo_mine, r);
                bits |= (val >= lo_r ? 1u : 0u) << r;
            }
        } else {
            #pragma unroll 8
            for (int r = 0; r < 32; r++) {
                int c = j * 32 + r;
                float2 v = __ldcg(reinterpret_cast<const float2*>(base + r * rowstep) + k);
                float val = half ? v.y : v.x;
                bool pred = (val >= g_lo[c]) && (val <= g_hi[c]);
                bits |= (pred ? 1u : 0u) << r;
            }
        }
        if (lane < OW) sa[lane * NW + j] = bits;
    }

    // ---- stage weights (L2-hot after first wave) ----
    {
        const uint4* wsrc = reinterpret_cast<const uint4*>(&g_wpack[half * CO][0]);
        #pragma unroll
        for (int i = 0; i < (CO * NW / 4) / 256; i++)
            sw4[i * 256 + threadIdx.x] = wsrc[i * 256 + threadIdx.x];
    }
    __syncthreads();

    // ---- Phase B: popcount GEMM (vector LDS) ----
    if (lane >= OW) return;

    uint4 av0 = sa4[lane * 2 + 0];
    uint4 av1 = sa4[lane * 2 + 1];
    unsigned a0 = av0.x, a1 = av0.y, a2 = av0.z, a3 = av0.w;
    unsigned a4 = av1.x, a5 = av1.y, a6 = av1.z, a7 = av1.w;

    float* op = out + ((((size_t)b * 2 * CO + half * CO) * OH + oh) * OW) + lane;
    #pragma unroll 8
    for (int oo = 0; oo < CO / 8; oo++) {
        int o = oo * 8 + j;
        uint4 wv0 = sw4[o * 2 + 0];
        uint4 wv1 = sw4[o * 2 + 1];
        int s = __popc(a0 ^ wv0.x) + __popc(a1 ^ wv0.y)
              + __popc(a2 ^ wv0.z) + __popc(a3 ^ wv0.w)
              + __popc(a4 ^ wv1.x) + __popc(a5 ^ wv1.y)
              + __popc(a6 ^ wv1.z) + __popc(a7 ^ wv1.w);
        op[(size_t)o * (OH * OW)] = (float)(C - 2 * s);
    }
}

// ============================================================
extern "C" void kernel_launch(void* const* d_in, const int* in_sizes, int n_in,
                              void* d_out, int out_size) {
    const float* x     = (const float*)d_in[0];
    const float* gamma = (const float*)d_in[1];
    const float* beta  = (const float*)d_in[2];
    const float* w1    = (const float*)d_in[3];
    const float* w2    = (const float*)d_in[4];
    float* out = (float*)d_out;

    stats_wpack_kernel<<<1088, 256>>>(x, w1, w2, gamma, beta);
    fused_kernel<<<dim3(OH, B, 2), 256>>>(x, out);
}